// round 12
// baseline (speedup 1.0000x reference)
#include <cuda_runtime.h>
#include <cuda_fp16.h>
#include <math.h>
#include <stdint.h>

#define NTS      4096
#define SEQ_LEN  168
#define HORIZON  24
#define TTOT     (SEQ_LEN + HORIZON)
#define F_IN     32
#define EMBED    32
#define HIDDEN   64
#define LAYERS   2

#define BLK      128
#define GRID_B   1024                    /* 1024 x 4 warps = 4096 series */
#define NCTA_A   (NTS * SEQ_LEN / 256)   /* 2688 CTAs x 256 items (2/thread) */

/* ---- smem byte offsets ----
   OFF_W: A-role = fp32 [192][64] single-layer buffer (48 KB, reloaded)
          B-role = half2 [64][192] both layers packed (48 KB)            */
#define OFF_W       0
#define OFF_SB      49152                /* float[2][192] combined biases */
#define OFF_SWE     50688
#define OFF_SBE     50816
#define OFF_SWMU    50944
#define OFF_SWSG    51200
#define OFF_SH      51456                /* B role: 4 warps x 64 floats */
#define SMEM_TOTAL  (51456 + 1024)

typedef unsigned long long u64;

__device__ __forceinline__ float ex2f(float x) {
    float r; asm("ex2.approx.f32 %0, %1;" : "=f"(r) : "f"(x)); return r;
}
__device__ __forceinline__ float rcpf(float x) {
    float r; asm("rcp.approx.f32 %0, %1;" : "=f"(r) : "f"(x)); return r;
}
__device__ __forceinline__ float sigm(float x) {
    return rcpf(1.0f + ex2f(-1.4426950408889634f * x));
}
__device__ __forceinline__ float tanh_(float x) {
    return 1.0f - 2.0f * rcpf(1.0f + ex2f(2.8853900817779268f * x));
}
__device__ __forceinline__ float softplus_(float x) {
    return (x > 20.0f) ? x : log1pf(ex2f(1.4426950408889634f * x));
}
__device__ __forceinline__ int src_row(int r) { return r + ((r >= 64) ? 64 : 0); }

__device__ __forceinline__ u64 pack2(float lo, float hi) {
    u64 r; asm("mov.b64 %0, {%1,%2};" : "=l"(r) : "f"(lo), "f"(hi)); return r;
}
__device__ __forceinline__ void unpack2(u64 v, float& a, float& b) {
    asm("mov.b64 {%0,%1}, %2;" : "=f"(a), "=f"(b) : "l"(v));
}
__device__ __forceinline__ u64 ffma2(u64 a, u64 b, u64 c) {
    u64 d; asm("fma.rn.f32x2 %0, %1, %2, %3;" : "=l"(d) : "l"(a), "l"(b), "l"(c));
    return d;
}

__global__ void __launch_bounds__(BLK, 3) deepar_v12(
    const float* __restrict__ X, const float* __restrict__ y,
    const float* __restrict__ Xf,
    const float* __restrict__ W_embed, const float* __restrict__ b_embed,
    const float* __restrict__ W_ih, const float* __restrict__ b_ih,
    const float* __restrict__ b_hh,
    const float* __restrict__ W_mu, const float* __restrict__ b_mu,
    const float* __restrict__ W_sigma, const float* __restrict__ b_sigma,
    float* __restrict__ out)
{
    extern __shared__ char sm[];
    float* sB   = (float*)(sm + OFF_SB);
    float* sWe  = (float*)(sm + OFF_SWE);
    float* sBe  = (float*)(sm + OFF_SBE);
    float* sWmu = (float*)(sm + OFF_SWMU);
    float* sWsg = (float*)(sm + OFF_SWSG);

    const int tid  = threadIdx.x;
    const int lane = tid & 31;
    const int wid  = tid >> 5;
    const bool isB = (blockIdx.x < GRID_B);

    float* out_mu = out + NTS * HORIZON;
    float* out_sg = out_mu + NTS * TTOT;

    /* biases + small weights */
    for (int idx = tid; idx < 2 * 192; idx += BLK) {
        int l = idx / 192, r = idx % 192;
        int sr = l * 256 + src_row(r);
        sB[idx] = b_ih[sr] + b_hh[sr];
    }
    if (tid < 32) { sWe[tid] = W_embed[tid]; sBe[tid] = b_embed[tid]; }
    if (tid < 64) { sWmu[tid] = W_mu[tid]; sWsg[tid] = W_sigma[tid]; }

    if (isB) {
        /* ============ Phase B: horizon scan, 4 warps = 4 series ==========
           WT16[k][r] = half2(W_l0[r][k], W_l1[r][k])  (transposed)        */
        __half2* sWT16 = (__half2*)(sm + OFF_W);
        for (int idx = tid; idx < 64 * 192; idx += BLK) {
            int k = idx / 192, r = idx % 192;
            float w0 = W_ih[src_row(r) * 64 + k];
            float w1 = W_ih[16384 + src_row(r) * 64 + k];
            sWT16[idx] = __floats2half2_rn(w0, w1);
        }
        __syncthreads();

        const int n = blockIdx.x * 4 + wid;
        float* sh = (float*)(sm + OFF_SH) + wid * 64;
        const float bmu = b_mu[0], bsg = b_sigma[0];
        const float we = sWe[lane], be = sBe[lane];
        const float wmu0 = sWmu[lane], wmu1 = sWmu[32 + lane];
        const float wsg0 = sWsg[lane], wsg1 = sWsg[32 + lane];

        float carry = 0.0f;
        for (int sp = 0; sp <= HORIZON; ++sp) {
            const bool seed = (sp == 0);
            const float yn = seed ? y[(size_t)n * SEQ_LEN + (SEQ_LEN - 1)] : carry;
            const float* xsrc = seed
                ? (X + ((size_t)n * SEQ_LEN + (SEQ_LEN - 1)) * F_IN)
                : (Xf + ((size_t)n * HORIZON + (sp - 1)) * F_IN);

            sh[lane]      = xsrc[lane];
            sh[32 + lane] = fmaf(yn, we, be);
            __syncwarp();

            #pragma unroll
            for (int l = 0; l < LAYERS; ++l) {
                const float* Bb = sB + l * 192;
                float a0 = Bb[lane],      a1 = Bb[64 + lane],  a2 = Bb[128 + lane];
                float a3 = Bb[32 + lane], a4 = Bb[96 + lane],  a5 = Bb[160 + lane];
                #pragma unroll 8
                for (int k = 0; k < 64; ++k) {
                    const float hk = sh[k];
                    const __half2* row = sWT16 + k * 192;
                    float w0, w1, w2, w3, w4, w5;
                    if (l == 0) {
                        w0 = __low2float(row[lane]);
                        w1 = __low2float(row[64 + lane]);
                        w2 = __low2float(row[128 + lane]);
                        w3 = __low2float(row[32 + lane]);
                        w4 = __low2float(row[96 + lane]);
                        w5 = __low2float(row[160 + lane]);
                    } else {
                        w0 = __high2float(row[lane]);
                        w1 = __high2float(row[64 + lane]);
                        w2 = __high2float(row[128 + lane]);
                        w3 = __high2float(row[32 + lane]);
                        w4 = __high2float(row[96 + lane]);
                        w5 = __high2float(row[160 + lane]);
                    }
                    a0 = fmaf(w0, hk, a0);
                    a1 = fmaf(w1, hk, a1);
                    a2 = fmaf(w2, hk, a2);
                    a3 = fmaf(w3, hk, a3);
                    a4 = fmaf(w4, hk, a4);
                    a5 = fmaf(w5, hk, a5);
                }
                float c0 = sigm(a0) * tanh_(a1);
                float h0 = sigm(a2) * tanh_(c0);
                float c1 = sigm(a3) * tanh_(a4);
                float h1 = sigm(a5) * tanh_(c1);
                __syncwarp();
                sh[lane] = h0; sh[32 + lane] = h1;
                __syncwarp();
            }

            float r0 = fmaxf(sh[lane], 0.0f), r1 = fmaxf(sh[32 + lane], 0.0f);
            float pm = r0 * wmu0 + r1 * wmu1;
            float ps = r0 * wsg0 + r1 * wsg1;
            #pragma unroll
            for (int off = 16; off; off >>= 1) {
                pm += __shfl_xor_sync(0xFFFFFFFFu, pm, off);
                ps += __shfl_xor_sync(0xFFFFFFFFu, ps, off);
            }
            float mu = pm + bmu;
            float sigma = softplus_(ps + bsg) + 1e-6f;
            float s2 = sigma * sigma;
            float d = yn - mu;
            float lik = rsqrtf(2.0f * (float)M_PI * s2) *
                        ex2f(-1.4426950408889634f * (d * d) / (2.0f * s2));

            if (lane == 0) {
                if (seed) {
                    out[n * HORIZON] = lik;
                } else {
                    const int t = SEQ_LEN + sp - 1;
                    out_mu[n * TTOT + t] = mu;
                    out_sg[n * TTOT + t] = sigma;
                    if (sp <= HORIZON - 1) out[n * HORIZON + sp] = lik;
                }
            }
            carry = lik;
        }
        return;
    }

    /* ============ Phase A: 2 items/thread, single-layer smem ============ */
    float* sW = (float*)(sm + OFF_W);   /* [192][64] current-layer, i,g,o */
    for (int idx = tid; idx < 192 * 64; idx += BLK) {
        int r = idx / 64, k = idx % 64;
        sW[idx] = W_ih[src_row(r) * 64 + k];   /* layer 0 */
    }
    __syncthreads();

    const int aBase = (blockIdx.x - GRID_B) * 256;
    const int mA = aBase + tid;
    const int mB = aBase + 128 + tid;

    u64 h2A[32], h2B[32];
    {
        const float4* xa = (const float4*)(X + (size_t)mA * F_IN);
        const float4* xb = (const float4*)(X + (size_t)mB * F_IN);
        #pragma unroll
        for (int q = 0; q < 8; ++q) {
            float4 va = xa[q], vb = xb[q];
            h2A[2 * q]     = pack2(va.x, va.y);
            h2A[2 * q + 1] = pack2(va.z, va.w);
            h2B[2 * q]     = pack2(vb.x, vb.y);
            h2B[2 * q + 1] = pack2(vb.z, vb.w);
        }
        const float ynA = y[mA], ynB = y[mB];
        #pragma unroll
        for (int e = 0; e < 16; ++e) {
            float w0 = sWe[2 * e], w1 = sWe[2 * e + 1];
            float b0 = sBe[2 * e], b1 = sBe[2 * e + 1];
            h2A[16 + e] = pack2(fmaf(ynA, w0, b0), fmaf(ynA, w1, b1));
            h2B[16 + e] = pack2(fmaf(ynB, w0, b0), fmaf(ynB, w1, b1));
        }
    }

    /* ---------------- layer 1 -> hn16[j] = half2(hA[j], hB[j]) ---------- */
    uint32_t hn16[64];
    {
        const float* Bb = sB;
        #pragma unroll 1
        for (int j = 0; j < 64; ++j) {
            const ulonglong2* wi = (const ulonglong2*)(sW + j * 64);
            const ulonglong2* wg = (const ulonglong2*)(sW + (64 + j) * 64);
            const ulonglong2* wo = (const ulonglong2*)(sW + (128 + j) * 64);
            u64 aiA = pack2(Bb[j], 0.f),       aiB = aiA;
            u64 agA = pack2(Bb[64 + j], 0.f),  agB = agA;
            u64 aoA = pack2(Bb[128 + j], 0.f), aoB = aoA;
            #pragma unroll 8
            for (int q = 0; q < 16; ++q) {
                ulonglong2 vi = wi[q], vg = wg[q], vo = wo[q];
                u64 a0 = h2A[2 * q], a1 = h2A[2 * q + 1];
                u64 b0 = h2B[2 * q], b1 = h2B[2 * q + 1];
                aiA = ffma2(vi.x, a0, aiA); aiB = ffma2(vi.x, b0, aiB);
                agA = ffma2(vg.x, a0, agA); agB = ffma2(vg.x, b0, agB);
                aoA = ffma2(vo.x, a0, aoA); aoB = ffma2(vo.x, b0, aoB);
                aiA = ffma2(vi.y, a1, aiA); aiB = ffma2(vi.y, b1, aiB);
                agA = ffma2(vg.y, a1, agA); agB = ffma2(vg.y, b1, agB);
                aoA = ffma2(vo.y, a1, aoA); aoB = ffma2(vo.y, b1, aoB);
            }
            float x0, x1, g0, g1, o0, o1;
            unpack2(aiA, x0, x1); unpack2(agA, g0, g1); unpack2(aoA, o0, o1);
            float cA = sigm(x0 + x1) * tanh_(g0 + g1);
            float hA = sigm(o0 + o1) * tanh_(cA);
            unpack2(aiB, x0, x1); unpack2(agB, g0, g1); unpack2(aoB, o0, o1);
            float cB = sigm(x0 + x1) * tanh_(g0 + g1);
            float hB = sigm(o0 + o1) * tanh_(cB);
            __half2 hh = __floats2half2_rn(hA, hB);
            hn16[j] = *(uint32_t*)&hh;
        }
    }

    /* ---- swap in layer-2 weights ---- */
    __syncthreads();
    for (int idx = tid; idx < 192 * 64; idx += BLK) {
        int r = idx / 64, k = idx % 64;
        sW[idx] = W_ih[16384 + src_row(r) * 64 + k];   /* layer 1 */
    }

    /* unpack hn16 -> h2A/h2B while the reload settles */
    #pragma unroll
    for (int kp = 0; kp < 32; ++kp) {
        __half2 p0 = *(__half2*)&hn16[2 * kp];
        __half2 p1 = *(__half2*)&hn16[2 * kp + 1];
        float2 f0 = __half22float2(p0);
        float2 f1 = __half22float2(p1);
        h2A[kp] = pack2(f0.x, f1.x);
        h2B[kp] = pack2(f0.y, f1.y);
    }
    __syncthreads();

    /* ---------------- layer 2 + fused head ------------------------------ */
    float pmA = 0.f, psA = 0.f, pmB = 0.f, psB = 0.f;
    {
        const float* Bb = sB + 192;
        #pragma unroll 1
        for (int j = 0; j < 64; ++j) {
            const ulonglong2* wi = (const ulonglong2*)(sW + j * 64);
            const ulonglong2* wg = (const ulonglong2*)(sW + (64 + j) * 64);
            const ulonglong2* wo = (const ulonglong2*)(sW + (128 + j) * 64);
            u64 aiA = pack2(Bb[j], 0.f),       aiB = aiA;
            u64 agA = pack2(Bb[64 + j], 0.f),  agB = agA;
            u64 aoA = pack2(Bb[128 + j], 0.f), aoB = aoA;
            #pragma unroll 8
            for (int q = 0; q < 16; ++q) {
                ulonglong2 vi = wi[q], vg = wg[q], vo = wo[q];
                u64 a0 = h2A[2 * q], a1 = h2A[2 * q + 1];
                u64 b0 = h2B[2 * q], b1 = h2B[2 * q + 1];
                aiA = ffma2(vi.x, a0, aiA); aiB = ffma2(vi.x, b0, aiB);
                agA = ffma2(vg.x, a0, agA); agB = ffma2(vg.x, b0, agB);
                aoA = ffma2(vo.x, a0, aoA); aoB = ffma2(vo.x, b0, aoB);
                aiA = ffma2(vi.y, a1, aiA); aiB = ffma2(vi.y, b1, aiB);
                agA = ffma2(vg.y, a1, agA); agB = ffma2(vg.y, b1, agB);
                aoA = ffma2(vo.y, a1, aoA); aoB = ffma2(vo.y, b1, aoB);
            }
            float x0, x1, g0, g1, o0, o1;
            unpack2(aiA, x0, x1); unpack2(agA, g0, g1); unpack2(aoA, o0, o1);
            float cA = sigm(x0 + x1) * tanh_(g0 + g1);
            float hA = sigm(o0 + o1) * tanh_(cA);
            unpack2(aiB, x0, x1); unpack2(agB, g0, g1); unpack2(aoB, o0, o1);
            float cB = sigm(x0 + x1) * tanh_(g0 + g1);
            float hB = sigm(o0 + o1) * tanh_(cB);
            float rA = fmaxf(hA, 0.0f), rB = fmaxf(hB, 0.0f);
            float wm = sWmu[j], ws = sWsg[j];
            pmA = fmaf(rA, wm, pmA); pmB = fmaf(rB, wm, pmB);
            psA = fmaf(rA, ws, psA); psB = fmaf(rB, ws, psB);
        }
    }

    const float bmu = b_mu[0], bsg = b_sigma[0];
    {
        const int n = mA / SEQ_LEN, t = mA % SEQ_LEN;
        out_mu[n * TTOT + t] = pmA + bmu;
        out_sg[n * TTOT + t] = softplus_(psA + bsg) + 1e-6f;
    }
    {
        const int n = mB / SEQ_LEN, t = mB % SEQ_LEN;
        out_mu[n * TTOT + t] = pmB + bmu;
        out_sg[n * TTOT + t] = softplus_(psB + bsg) + 1e-6f;
    }
}

extern "C" void kernel_launch(void* const* d_in, const int* in_sizes, int n_in,
                              void* d_out, int out_size)
{
    const float* X       = (const float*)d_in[0];
    const float* y       = (const float*)d_in[1];
    const float* Xf      = (const float*)d_in[2];
    const float* W_embed = (const float*)d_in[3];
    const float* b_embed = (const float*)d_in[4];
    const float* W_ih    = (const float*)d_in[5];
    const float* b_ih    = (const float*)d_in[6];
    const float* b_hh    = (const float*)d_in[7];
    const float* W_mu    = (const float*)d_in[8];
    const float* b_mu    = (const float*)d_in[9];
    const float* W_sigma = (const float*)d_in[10];
    const float* b_sigma = (const float*)d_in[11];
    float* out = (float*)d_out;

    static bool attr_done = false;
    if (!attr_done) {
        cudaFuncSetAttribute(deepar_v12,
            cudaFuncAttributeMaxDynamicSharedMemorySize, SMEM_TOTAL);
        attr_done = true;
    }

    deepar_v12<<<GRID_B + NCTA_A, BLK, SMEM_TOTAL>>>(
        X, y, Xf, W_embed, b_embed, W_ih, b_ih, b_hh,
        W_mu, b_mu, W_sigma, b_sigma, out);
}

// round 13
// speedup vs baseline: 1.4044x; 1.4044x over previous
#include <cuda_runtime.h>
#include <cuda_fp16.h>
#include <math.h>
#include <stdint.h>

#define NTS      4096
#define SEQ_LEN  168
#define HORIZON  24
#define TTOT     (SEQ_LEN + HORIZON)
#define F_IN     32
#define EMBED    32
#define HIDDEN   64
#define LAYERS   2

#define BLK      128
#define GRID_B   1024                    /* 1024 x 4 warps = 4096 series */
#define NCTA_A   (NTS * SEQ_LEN / 256)   /* 2688 CTAs x 256 items (2/thread) */

/* ---- smem byte offsets ---- */
#define OFF_W       0                    /* A: [2][192][64] row-major; B: WT transposed */
#define OFF_SB      98304                /* float[2][192] combined biases */
#define OFF_SWE     99840
#define OFF_SBE     99968
#define OFF_SWMU    100096
#define OFF_SWSG    100352
#define OFF_SH      100608               /* B role: 4 warps x 64 floats */
#define SMEM_TOTAL  (100608 + 1024)

typedef unsigned long long u64;

__device__ __forceinline__ float ex2f(float x) {
    float r; asm("ex2.approx.f32 %0, %1;" : "=f"(r) : "f"(x)); return r;
}
__device__ __forceinline__ float rcpf(float x) {
    float r; asm("rcp.approx.f32 %0, %1;" : "=f"(r) : "f"(x)); return r;
}
__device__ __forceinline__ float sigm(float x) {
    return rcpf(1.0f + ex2f(-1.4426950408889634f * x));
}
__device__ __forceinline__ float tanh_(float x) {
    return 1.0f - 2.0f * rcpf(1.0f + ex2f(2.8853900817779268f * x));
}
__device__ __forceinline__ float softplus_(float x) {
    return (x > 20.0f) ? x : log1pf(ex2f(1.4426950408889634f * x));
}
__device__ __forceinline__ int src_row(int r) { return r + ((r >= 64) ? 64 : 0); }

__device__ __forceinline__ u64 pack2(float lo, float hi) {
    u64 r; asm("mov.b64 %0, {%1,%2};" : "=l"(r) : "f"(lo), "f"(hi)); return r;
}
__device__ __forceinline__ void unpack2(u64 v, float& a, float& b) {
    asm("mov.b64 {%0,%1}, %2;" : "=f"(a), "=f"(b) : "l"(v));
}
__device__ __forceinline__ u64 ffma2(u64 a, u64 b, u64 c) {
    u64 d; asm("fma.rn.f32x2 %0, %1, %2, %3;" : "=l"(d) : "l"(a), "l"(b), "l"(c));
    return d;
}

/* one j-column GEMM micro-kernel body: 6 chains over 16 q-steps */
struct Acc6 { u64 ai_, ag_, ao_, bi_, bg_, bo_; };

__device__ __forceinline__ void gate_act(u64 ai, u64 ag, u64 ao,
                                         float& h) {
    float x0, x1, g0, g1, o0, o1;
    unpack2(ai, x0, x1); unpack2(ag, g0, g1); unpack2(ao, o0, o1);
    float c = sigm(x0 + x1) * tanh_(g0 + g1);
    h = sigm(o0 + o1) * tanh_(c);
}

__global__ void __launch_bounds__(BLK, 2) deepar_v13(
    const float* __restrict__ X, const float* __restrict__ y,
    const float* __restrict__ Xf,
    const float* __restrict__ W_embed, const float* __restrict__ b_embed,
    const float* __restrict__ W_ih, const float* __restrict__ b_ih,
    const float* __restrict__ b_hh,
    const float* __restrict__ W_mu, const float* __restrict__ b_mu,
    const float* __restrict__ W_sigma, const float* __restrict__ b_sigma,
    float* __restrict__ out)
{
    extern __shared__ char sm[];
    float* sB   = (float*)(sm + OFF_SB);
    float* sWe  = (float*)(sm + OFF_SWE);
    float* sBe  = (float*)(sm + OFF_SBE);
    float* sWmu = (float*)(sm + OFF_SWMU);
    float* sWsg = (float*)(sm + OFF_SWSG);

    const int tid  = threadIdx.x;
    const int lane = tid & 31;
    const int wid  = tid >> 5;
    const bool isB = (blockIdx.x < GRID_B);

    float* out_mu = out + NTS * HORIZON;
    float* out_sg = out_mu + NTS * TTOT;

    for (int idx = tid; idx < 2 * 192; idx += BLK) {
        int l = idx / 192, r = idx % 192;
        int sr = l * 256 + src_row(r);
        sB[idx] = b_ih[sr] + b_hh[sr];
    }
    if (tid < 32) { sWe[tid] = W_embed[tid]; sBe[tid] = b_embed[tid]; }
    if (tid < 64) { sWmu[tid] = W_mu[tid]; sWsg[tid] = W_sigma[tid]; }

    if (isB) {
        /* ============ Phase B: horizon scan, 4 warps = 4 series ========== */
        float* sWT = (float*)(sm + OFF_W);      /* [2][64][192] transposed */
        for (int idx = tid; idx < 2 * 192 * 64; idx += BLK) {
            int l = idx / 12288, rem = idx % 12288;
            int r = rem / 64, k = rem % 64;
            sWT[l * 12288 + k * 192 + r] = W_ih[l * 16384 + src_row(r) * 64 + k];
        }
        __syncthreads();

        const int n = blockIdx.x * 4 + wid;
        float* sh = (float*)(sm + OFF_SH) + wid * 64;
        const float bmu = b_mu[0], bsg = b_sigma[0];
        const float we = sWe[lane], be = sBe[lane];
        const float wmu0 = sWmu[lane], wmu1 = sWmu[32 + lane];
        const float wsg0 = sWsg[lane], wsg1 = sWsg[32 + lane];

        float carry = 0.0f;
        for (int sp = 0; sp <= HORIZON; ++sp) {
            const bool seed = (sp == 0);
            const float yn = seed ? y[(size_t)n * SEQ_LEN + (SEQ_LEN - 1)] : carry;
            const float* xsrc = seed
                ? (X + ((size_t)n * SEQ_LEN + (SEQ_LEN - 1)) * F_IN)
                : (Xf + ((size_t)n * HORIZON + (sp - 1)) * F_IN);

            sh[lane]      = xsrc[lane];
            sh[32 + lane] = fmaf(yn, we, be);
            __syncwarp();

            #pragma unroll
            for (int l = 0; l < LAYERS; ++l) {
                const float* WT = sWT + l * 12288;
                const float* Bb = sB + l * 192;
                float a0 = Bb[lane],      a1 = Bb[64 + lane],  a2 = Bb[128 + lane];
                float a3 = Bb[32 + lane], a4 = Bb[96 + lane],  a5 = Bb[160 + lane];
                #pragma unroll
                for (int k = 0; k < 64; ++k) {
                    const float hk = sh[k];
                    const float* row = WT + k * 192;
                    a0 = fmaf(row[lane],       hk, a0);
                    a1 = fmaf(row[64 + lane],  hk, a1);
                    a2 = fmaf(row[128 + lane], hk, a2);
                    a3 = fmaf(row[32 + lane],  hk, a3);
                    a4 = fmaf(row[96 + lane],  hk, a4);
                    a5 = fmaf(row[160 + lane], hk, a5);
                }
                float c0 = sigm(a0) * tanh_(a1);
                float h0 = sigm(a2) * tanh_(c0);
                float c1 = sigm(a3) * tanh_(a4);
                float h1 = sigm(a5) * tanh_(c1);
                __syncwarp();
                sh[lane] = h0; sh[32 + lane] = h1;
                __syncwarp();
            }

            float r0 = fmaxf(sh[lane], 0.0f), r1 = fmaxf(sh[32 + lane], 0.0f);
            float pm = r0 * wmu0 + r1 * wmu1;
            float ps = r0 * wsg0 + r1 * wsg1;
            #pragma unroll
            for (int off = 16; off; off >>= 1) {
                pm += __shfl_xor_sync(0xFFFFFFFFu, pm, off);
                ps += __shfl_xor_sync(0xFFFFFFFFu, ps, off);
            }
            float mu = pm + bmu;
            float sigma = softplus_(ps + bsg) + 1e-6f;
            float s2 = sigma * sigma;
            float d = yn - mu;
            float lik = rsqrtf(2.0f * (float)M_PI * s2) *
                        ex2f(-1.4426950408889634f * (d * d) / (2.0f * s2));

            if (lane == 0) {
                if (seed) {
                    out[n * HORIZON] = lik;
                } else {
                    const int t = SEQ_LEN + sp - 1;
                    out_mu[n * TTOT + t] = mu;
                    out_sg[n * TTOT + t] = sigma;
                    if (sp <= HORIZON - 1) out[n * HORIZON + sp] = lik;
                }
            }
            carry = lik;
        }
        return;
    }

    /* ============ Phase A: 2 items/thread, 2 j's per iteration =========== */
    float* sW = (float*)(sm + OFF_W);   /* [2][192][64] row-major i,g,o */
    for (int idx = tid; idx < 2 * 192 * 64; idx += BLK) {
        int l = idx / 12288, rem = idx % 12288;
        int r = rem / 64, k = rem % 64;
        sW[idx] = W_ih[l * 16384 + src_row(r) * 64 + k];
    }
    __syncthreads();

    const int aBase = (blockIdx.x - GRID_B) * 256;
    const int mA = aBase + tid;
    const int mB = aBase + 128 + tid;

    u64 h2A[32], h2B[32];
    {
        const float4* xa = (const float4*)(X + (size_t)mA * F_IN);
        const float4* xb = (const float4*)(X + (size_t)mB * F_IN);
        #pragma unroll
        for (int q = 0; q < 8; ++q) {
            float4 va = xa[q], vb = xb[q];
            h2A[2 * q]     = pack2(va.x, va.y);
            h2A[2 * q + 1] = pack2(va.z, va.w);
            h2B[2 * q]     = pack2(vb.x, vb.y);
            h2B[2 * q + 1] = pack2(vb.z, vb.w);
        }
        const float ynA = y[mA], ynB = y[mB];
        #pragma unroll
        for (int e = 0; e < 16; ++e) {
            float w0 = sWe[2 * e], w1 = sWe[2 * e + 1];
            float b0 = sBe[2 * e], b1 = sBe[2 * e + 1];
            h2A[16 + e] = pack2(fmaf(ynA, w0, b0), fmaf(ynA, w1, b1));
            h2B[16 + e] = pack2(fmaf(ynB, w0, b0), fmaf(ynB, w1, b1));
        }
    }

    /* ---------------- layer 1: j and j+32 per iteration ----------------- */
    uint32_t hn16[64];
    {
        const float* Bb = sB;
        #pragma unroll 1
        for (int j = 0; j < 32; ++j) {
            const int j2 = j + 32;
            const ulonglong2* wi0 = (const ulonglong2*)(sW + j * 64);
            const ulonglong2* wg0 = (const ulonglong2*)(sW + (64 + j) * 64);
            const ulonglong2* wo0 = (const ulonglong2*)(sW + (128 + j) * 64);
            const ulonglong2* wi1 = (const ulonglong2*)(sW + j2 * 64);
            const ulonglong2* wg1 = (const ulonglong2*)(sW + (64 + j2) * 64);
            const ulonglong2* wo1 = (const ulonglong2*)(sW + (128 + j2) * 64);
            u64 aiA0 = pack2(Bb[j], 0.f),        aiB0 = aiA0;
            u64 agA0 = pack2(Bb[64 + j], 0.f),   agB0 = agA0;
            u64 aoA0 = pack2(Bb[128 + j], 0.f),  aoB0 = aoA0;
            u64 aiA1 = pack2(Bb[j2], 0.f),       aiB1 = aiA1;
            u64 agA1 = pack2(Bb[64 + j2], 0.f),  agB1 = agA1;
            u64 aoA1 = pack2(Bb[128 + j2], 0.f), aoB1 = aoA1;
            #pragma unroll
            for (int q = 0; q < 16; ++q) {
                ulonglong2 vi0 = wi0[q], vg0 = wg0[q], vo0 = wo0[q];
                ulonglong2 vi1 = wi1[q], vg1 = wg1[q], vo1 = wo1[q];
                u64 a0 = h2A[2 * q], a1 = h2A[2 * q + 1];
                u64 b0 = h2B[2 * q], b1 = h2B[2 * q + 1];
                aiA0 = ffma2(vi0.x, a0, aiA0); aiB0 = ffma2(vi0.x, b0, aiB0);
                agA0 = ffma2(vg0.x, a0, agA0); agB0 = ffma2(vg0.x, b0, agB0);
                aoA0 = ffma2(vo0.x, a0, aoA0); aoB0 = ffma2(vo0.x, b0, aoB0);
                aiA1 = ffma2(vi1.x, a0, aiA1); aiB1 = ffma2(vi1.x, b0, aiB1);
                agA1 = ffma2(vg1.x, a0, agA1); agB1 = ffma2(vg1.x, b0, agB1);
                aoA1 = ffma2(vo1.x, a0, aoA1); aoB1 = ffma2(vo1.x, b0, aoB1);
                aiA0 = ffma2(vi0.y, a1, aiA0); aiB0 = ffma2(vi0.y, b1, aiB0);
                agA0 = ffma2(vg0.y, a1, agA0); agB0 = ffma2(vg0.y, b1, agB0);
                aoA0 = ffma2(vo0.y, a1, aoA0); aoB0 = ffma2(vo0.y, b1, aoB0);
                aiA1 = ffma2(vi1.y, a1, aiA1); aiB1 = ffma2(vi1.y, b1, aiB1);
                agA1 = ffma2(vg1.y, a1, agA1); agB1 = ffma2(vg1.y, b1, agB1);
                aoA1 = ffma2(vo1.y, a1, aoA1); aoB1 = ffma2(vo1.y, b1, aoB1);
            }
            float hA0, hB0, hA1, hB1;
            gate_act(aiA0, agA0, aoA0, hA0);
            gate_act(aiB0, agB0, aoB0, hB0);
            gate_act(aiA1, agA1, aoA1, hA1);
            gate_act(aiB1, agB1, aoB1, hB1);
            __half2 p0 = __floats2half2_rn(hA0, hB0);
            __half2 p1 = __floats2half2_rn(hA1, hB1);
            hn16[j]  = *(uint32_t*)&p0;
            hn16[j2] = *(uint32_t*)&p1;
        }
    }

    /* unpack hn16 -> h2A/h2B (f32 k-pair packing) */
    #pragma unroll
    for (int kp = 0; kp < 32; ++kp) {
        __half2 p0 = *(__half2*)&hn16[2 * kp];
        __half2 p1 = *(__half2*)&hn16[2 * kp + 1];
        float2 f0 = __half22float2(p0);
        float2 f1 = __half22float2(p1);
        h2A[kp] = pack2(f0.x, f1.x);
        h2B[kp] = pack2(f0.y, f1.y);
    }

    /* ---------------- layer 2 + fused head (paired j's) ----------------- */
    float pmA = 0.f, psA = 0.f, pmB = 0.f, psB = 0.f;
    {
        const float* W = sW + 12288;
        const float* Bb = sB + 192;
        #pragma unroll 1
        for (int j = 0; j < 32; ++j) {
            const int j2 = j + 32;
            const ulonglong2* wi0 = (const ulonglong2*)(W + j * 64);
            const ulonglong2* wg0 = (const ulonglong2*)(W + (64 + j) * 64);
            const ulonglong2* wo0 = (const ulonglong2*)(W + (128 + j) * 64);
            const ulonglong2* wi1 = (const ulonglong2*)(W + j2 * 64);
            const ulonglong2* wg1 = (const ulonglong2*)(W + (64 + j2) * 64);
            const ulonglong2* wo1 = (const ulonglong2*)(W + (128 + j2) * 64);
            u64 aiA0 = pack2(Bb[j], 0.f),        aiB0 = aiA0;
            u64 agA0 = pack2(Bb[64 + j], 0.f),   agB0 = agA0;
            u64 aoA0 = pack2(Bb[128 + j], 0.f),  aoB0 = aoA0;
            u64 aiA1 = pack2(Bb[j2], 0.f),       aiB1 = aiA1;
            u64 agA1 = pack2(Bb[64 + j2], 0.f),  agB1 = agA1;
            u64 aoA1 = pack2(Bb[128 + j2], 0.f), aoB1 = aoA1;
            #pragma unroll
            for (int q = 0; q < 16; ++q) {
                ulonglong2 vi0 = wi0[q], vg0 = wg0[q], vo0 = wo0[q];
                ulonglong2 vi1 = wi1[q], vg1 = wg1[q], vo1 = wo1[q];
                u64 a0 = h2A[2 * q], a1 = h2A[2 * q + 1];
                u64 b0 = h2B[2 * q], b1 = h2B[2 * q + 1];
                aiA0 = ffma2(vi0.x, a0, aiA0); aiB0 = ffma2(vi0.x, b0, aiB0);
                agA0 = ffma2(vg0.x, a0, agA0); agB0 = ffma2(vg0.x, b0, agB0);
                aoA0 = ffma2(vo0.x, a0, aoA0); aoB0 = ffma2(vo0.x, b0, aoB0);
                aiA1 = ffma2(vi1.x, a0, aiA1); aiB1 = ffma2(vi1.x, b0, aiB1);
                agA1 = ffma2(vg1.x, a0, agA1); agB1 = ffma2(vg1.x, b0, agB1);
                aoA1 = ffma2(vo1.x, a0, aoA1); aoB1 = ffma2(vo1.x, b0, aoB1);
                aiA0 = ffma2(vi0.y, a1, aiA0); aiB0 = ffma2(vi0.y, b1, aiB0);
                agA0 = ffma2(vg0.y, a1, agA0); agB0 = ffma2(vg0.y, b1, agB0);
                aoA0 = ffma2(vo0.y, a1, aoA0); aoB0 = ffma2(vo0.y, b1, aoB0);
                aiA1 = ffma2(vi1.y, a1, aiA1); aiB1 = ffma2(vi1.y, b1, aiB1);
                agA1 = ffma2(vg1.y, a1, agA1); agB1 = ffma2(vg1.y, b1, agB1);
                aoA1 = ffma2(vo1.y, a1, aoA1); aoB1 = ffma2(vo1.y, b1, aoB1);
            }
            float hA0, hB0, hA1, hB1;
            gate_act(aiA0, agA0, aoA0, hA0);
            gate_act(aiB0, agB0, aoB0, hB0);
            gate_act(aiA1, agA1, aoA1, hA1);
            gate_act(aiB1, agB1, aoB1, hB1);
            float rA0 = fmaxf(hA0, 0.f), rB0 = fmaxf(hB0, 0.f);
            float rA1 = fmaxf(hA1, 0.f), rB1 = fmaxf(hB1, 0.f);
            float wm0 = sWmu[j], ws0 = sWsg[j];
            float wm1 = sWmu[j2], ws1 = sWsg[j2];
            pmA = fmaf(rA0, wm0, pmA); pmA = fmaf(rA1, wm1, pmA);
            pmB = fmaf(rB0, wm0, pmB); pmB = fmaf(rB1, wm1, pmB);
            psA = fmaf(rA0, ws0, psA); psA = fmaf(rA1, ws1, psA);
            psB = fmaf(rB0, ws0, psB); psB = fmaf(rB1, ws1, psB);
        }
    }

    const float bmu = b_mu[0], bsg = b_sigma[0];
    {
        const int n = mA / SEQ_LEN, t = mA % SEQ_LEN;
        out_mu[n * TTOT + t] = pmA + bmu;
        out_sg[n * TTOT + t] = softplus_(psA + bsg) + 1e-6f;
    }
    {
        const int n = mB / SEQ_LEN, t = mB % SEQ_LEN;
        out_mu[n * TTOT + t] = pmB + bmu;
        out_sg[n * TTOT + t] = softplus_(psB + bsg) + 1e-6f;
    }
}

extern "C" void kernel_launch(void* const* d_in, const int* in_sizes, int n_in,
                              void* d_out, int out_size)
{
    const float* X       = (const float*)d_in[0];
    const float* y       = (const float*)d_in[1];
    const float* Xf      = (const float*)d_in[2];
    const float* W_embed = (const float*)d_in[3];
    const float* b_embed = (const float*)d_in[4];
    const float* W_ih    = (const float*)d_in[5];
    const float* b_ih    = (const float*)d_in[6];
    const float* b_hh    = (const float*)d_in[7];
    const float* W_mu    = (const float*)d_in[8];
    const float* b_mu    = (const float*)d_in[9];
    const float* W_sigma = (const float*)d_in[10];
    const float* b_sigma = (const float*)d_in[11];
    float* out = (float*)d_out;

    static bool attr_done = false;
    if (!attr_done) {
        cudaFuncSetAttribute(deepar_v13,
            cudaFuncAttributeMaxDynamicSharedMemorySize, SMEM_TOTAL);
        attr_done = true;
    }

    deepar_v13<<<GRID_B + NCTA_A, BLK, SMEM_TOTAL>>>(
        X, y, Xf, W_embed, b_embed, W_ih, b_ih, b_hh,
        W_mu, b_mu, W_sigma, b_sigma, out);
}

// round 14
// speedup vs baseline: 1.5369x; 1.0943x over previous
#include <cuda_runtime.h>
#include <cuda_fp16.h>
#include <math.h>
#include <stdint.h>

#define NTS      4096
#define SEQ_LEN  168
#define HORIZON  24
#define TTOT     (SEQ_LEN + HORIZON)
#define F_IN     32
#define EMBED    32
#define HIDDEN   64
#define LAYERS   2

#define BLK      128
#define GRID_B   1024                    /* 1024 x 4 warps = 4096 series */
#define NCTA_A   (NTS * SEQ_LEN / 256)   /* 2688 CTAs x 256 items (2/thread) */

/* ---- smem byte offsets ----
   W1: A = [192][32] f32 (x-part only);  B = [32][192] transposed
   W2: A = [192][64] f32;                B = [64][192] transposed          */
#define OFF_W1      0
#define OFF_W2      24576
#define OFF_V       73728                /* f32[192] rank-1 y coefficient */
#define OFF_C       74496                /* f32[192] folded layer-1 bias  */
#define OFF_B2      75264                /* f32[192] layer-2 bias         */
#define OFF_SWE     76032
#define OFF_SBE     76160
#define OFF_SWMU    76288
#define OFF_SWSG    76544
#define OFF_SH      76800                /* B role: 4 warps x 64 floats   */
#define SMEM_TOTAL  77824

typedef unsigned long long u64;

__device__ __forceinline__ float ex2f(float x) {
    float r; asm("ex2.approx.f32 %0, %1;" : "=f"(r) : "f"(x)); return r;
}
__device__ __forceinline__ float rcpf(float x) {
    float r; asm("rcp.approx.f32 %0, %1;" : "=f"(r) : "f"(x)); return r;
}
__device__ __forceinline__ float sigm(float x) {
    return rcpf(1.0f + ex2f(-1.4426950408889634f * x));
}
__device__ __forceinline__ float tanh_(float x) {
    return 1.0f - 2.0f * rcpf(1.0f + ex2f(2.8853900817779268f * x));
}
__device__ __forceinline__ float softplus_(float x) {
    return (x > 20.0f) ? x : log1pf(ex2f(1.4426950408889634f * x));
}
__device__ __forceinline__ int src_row(int r) { return r + ((r >= 64) ? 64 : 0); }

__device__ __forceinline__ u64 pack2(float lo, float hi) {
    u64 r; asm("mov.b64 %0, {%1,%2};" : "=l"(r) : "f"(lo), "f"(hi)); return r;
}
__device__ __forceinline__ void unpack2(u64 v, float& a, float& b) {
    asm("mov.b64 {%0,%1}, %2;" : "=f"(a), "=f"(b) : "l"(v));
}
__device__ __forceinline__ u64 ffma2(u64 a, u64 b, u64 c) {
    u64 d; asm("fma.rn.f32x2 %0, %1, %2, %3;" : "=l"(d) : "l"(a), "l"(b), "l"(c));
    return d;
}

__device__ __forceinline__ void gate_act(u64 ai, u64 ag, u64 ao, float& h) {
    float x0, x1, g0, g1, o0, o1;
    unpack2(ai, x0, x1); unpack2(ag, g0, g1); unpack2(ao, o0, o1);
    float c = sigm(x0 + x1) * tanh_(g0 + g1);
    h = sigm(o0 + o1) * tanh_(c);
}

__global__ void __launch_bounds__(BLK, 2) deepar_v14(
    const float* __restrict__ X, const float* __restrict__ y,
    const float* __restrict__ Xf,
    const float* __restrict__ W_embed, const float* __restrict__ b_embed,
    const float* __restrict__ W_ih, const float* __restrict__ b_ih,
    const float* __restrict__ b_hh,
    const float* __restrict__ W_mu, const float* __restrict__ b_mu,
    const float* __restrict__ W_sigma, const float* __restrict__ b_sigma,
    float* __restrict__ out)
{
    extern __shared__ char sm[];
    float* sV   = (float*)(sm + OFF_V);
    float* sC   = (float*)(sm + OFF_C);
    float* sB2  = (float*)(sm + OFF_B2);
    float* sWe  = (float*)(sm + OFF_SWE);
    float* sBe  = (float*)(sm + OFF_SBE);
    float* sWmu = (float*)(sm + OFF_SWMU);
    float* sWsg = (float*)(sm + OFF_SWSG);

    const int tid  = threadIdx.x;
    const int lane = tid & 31;
    const int wid  = tid >> 5;
    const bool isB = (blockIdx.x < GRID_B);

    float* out_mu = out + NTS * HORIZON;
    float* out_sg = out_mu + NTS * TTOT;

    if (tid < 32) { sWe[tid] = W_embed[tid]; sBe[tid] = b_embed[tid]; }
    if (tid < 64) { sWmu[tid] = W_mu[tid]; sWsg[tid] = W_sigma[tid]; }

    /* ---- rank-1 fold for layer 1: v[r] = W1y@We, c[r] = W1y@be + bias --- */
    for (int r = tid; r < 192; r += BLK) {
        int sr = src_row(r);
        const float* wy = W_ih + sr * 64 + 32;
        float v = 0.f, c = b_ih[sr] + b_hh[sr];
        #pragma unroll
        for (int e = 0; e < 32; ++e) {
            v = fmaf(wy[e], W_embed[e], v);
            c = fmaf(wy[e], b_embed[e], c);
        }
        sV[r] = v; sC[r] = c;
    }
    /* layer-2 bias */
    for (int r = tid; r < 192; r += BLK) {
        int sr = 256 + src_row(r);
        sB2[r] = b_ih[sr] + b_hh[sr];
    }

    if (isB) {
        /* ============ Phase B: horizon scan, 4 warps = 4 series ========== */
        float* sWT1 = (float*)(sm + OFF_W1);    /* [32][192] x-part transposed */
        float* sWT2 = (float*)(sm + OFF_W2);    /* [64][192] transposed */
        for (int idx = tid; idx < 32 * 192; idx += BLK) {
            int k = idx / 192, r = idx % 192;
            sWT1[idx] = W_ih[src_row(r) * 64 + k];
        }
        for (int idx = tid; idx < 64 * 192; idx += BLK) {
            int k = idx / 192, r = idx % 192;
            sWT2[idx] = W_ih[16384 + src_row(r) * 64 + k];
        }
        __syncthreads();

        const int n = blockIdx.x * 4 + wid;
        float* sh = (float*)(sm + OFF_SH) + wid * 64;
        const float bmu = b_mu[0], bsg = b_sigma[0];
        const float wmu0 = sWmu[lane], wmu1 = sWmu[32 + lane];
        const float wsg0 = sWsg[lane], wsg1 = sWsg[32 + lane];
        const float v0 = sV[lane],       v1 = sV[64 + lane],  v2 = sV[128 + lane];
        const float v3 = sV[32 + lane],  v4 = sV[96 + lane],  v5 = sV[160 + lane];
        const float c0 = sC[lane],       c1 = sC[64 + lane],  c2 = sC[128 + lane];
        const float c3 = sC[32 + lane],  c4 = sC[96 + lane],  c5 = sC[160 + lane];

        float carry = 0.0f;
        for (int sp = 0; sp <= HORIZON; ++sp) {
            const bool seed = (sp == 0);
            const float yn = seed ? y[(size_t)n * SEQ_LEN + (SEQ_LEN - 1)] : carry;
            const float* xsrc = seed
                ? (X + ((size_t)n * SEQ_LEN + (SEQ_LEN - 1)) * F_IN)
                : (Xf + ((size_t)n * HORIZON + (sp - 1)) * F_IN);

            sh[lane] = xsrc[lane];
            __syncwarp();

            /* ---- layer 1 (k = 0..31, x only; y folded via v,c) ---- */
            float a0 = fmaf(yn, v0, c0), a1 = fmaf(yn, v1, c1);
            float a2 = fmaf(yn, v2, c2), a3 = fmaf(yn, v3, c3);
            float a4 = fmaf(yn, v4, c4), a5 = fmaf(yn, v5, c5);
            #pragma unroll
            for (int k = 0; k < 32; ++k) {
                const float hk = sh[k];
                const float* row = sWT1 + k * 192;
                a0 = fmaf(row[lane],       hk, a0);
                a1 = fmaf(row[64 + lane],  hk, a1);
                a2 = fmaf(row[128 + lane], hk, a2);
                a3 = fmaf(row[32 + lane],  hk, a3);
                a4 = fmaf(row[96 + lane],  hk, a4);
                a5 = fmaf(row[160 + lane], hk, a5);
            }
            float cc0 = sigm(a0) * tanh_(a1);
            float h0  = sigm(a2) * tanh_(cc0);
            float cc1 = sigm(a3) * tanh_(a4);
            float h1  = sigm(a5) * tanh_(cc1);
            __syncwarp();
            sh[lane] = h0; sh[32 + lane] = h1;
            __syncwarp();

            /* ---- layer 2 (k = 0..63) ---- */
            a0 = sB2[lane];      a1 = sB2[64 + lane];  a2 = sB2[128 + lane];
            a3 = sB2[32 + lane]; a4 = sB2[96 + lane];  a5 = sB2[160 + lane];
            #pragma unroll
            for (int k = 0; k < 64; ++k) {
                const float hk = sh[k];
                const float* row = sWT2 + k * 192;
                a0 = fmaf(row[lane],       hk, a0);
                a1 = fmaf(row[64 + lane],  hk, a1);
                a2 = fmaf(row[128 + lane], hk, a2);
                a3 = fmaf(row[32 + lane],  hk, a3);
                a4 = fmaf(row[96 + lane],  hk, a4);
                a5 = fmaf(row[160 + lane], hk, a5);
            }
            cc0 = sigm(a0) * tanh_(a1);
            h0  = sigm(a2) * tanh_(cc0);
            cc1 = sigm(a3) * tanh_(a4);
            h1  = sigm(a5) * tanh_(cc1);

            float r0 = fmaxf(h0, 0.0f), r1 = fmaxf(h1, 0.0f);
            float pm = r0 * wmu0 + r1 * wmu1;
            float ps = r0 * wsg0 + r1 * wsg1;
            #pragma unroll
            for (int off = 16; off; off >>= 1) {
                pm += __shfl_xor_sync(0xFFFFFFFFu, pm, off);
                ps += __shfl_xor_sync(0xFFFFFFFFu, ps, off);
            }
            float mu = pm + bmu;
            float sigma = softplus_(ps + bsg) + 1e-6f;
            float s2 = sigma * sigma;
            float d = yn - mu;
            float lik = rsqrtf(2.0f * (float)M_PI * s2) *
                        ex2f(-1.4426950408889634f * (d * d) / (2.0f * s2));

            if (lane == 0) {
                if (seed) {
                    out[n * HORIZON] = lik;
                } else {
                    const int t = SEQ_LEN + sp - 1;
                    out_mu[n * TTOT + t] = mu;
                    out_sg[n * TTOT + t] = sigma;
                    if (sp <= HORIZON - 1) out[n * HORIZON + sp] = lik;
                }
            }
            carry = lik;
        }
        return;
    }

    /* ============ Phase A: 2 items/thread, rank-1 folded layer 1 ========= */
    float* sW1 = (float*)(sm + OFF_W1);   /* [192][32] x-part */
    float* sW2 = (float*)(sm + OFF_W2);   /* [192][64] */
    for (int idx = tid; idx < 192 * 32; idx += BLK) {
        int r = idx / 32, k = idx % 32;
        sW1[idx] = W_ih[src_row(r) * 64 + k];
    }
    for (int idx = tid; idx < 192 * 64; idx += BLK) {
        int r = idx / 64, k = idx % 64;
        sW2[idx] = W_ih[16384 + src_row(r) * 64 + k];
    }
    __syncthreads();

    const int aBase = (blockIdx.x - GRID_B) * 256;
    const int mA = aBase + tid;
    const int mB = aBase + 128 + tid;

    /* x packed per item over k-pairs: 32 floats = 16 u64 */
    u64 h2A[32], h2B[32];
    {
        const float4* xa = (const float4*)(X + (size_t)mA * F_IN);
        const float4* xb = (const float4*)(X + (size_t)mB * F_IN);
        #pragma unroll
        for (int q = 0; q < 8; ++q) {
            float4 va = xa[q], vb = xb[q];
            h2A[2 * q]     = pack2(va.x, va.y);
            h2A[2 * q + 1] = pack2(va.z, va.w);
            h2B[2 * q]     = pack2(vb.x, vb.y);
            h2B[2 * q + 1] = pack2(vb.z, vb.w);
        }
    }
    const float ynA = y[mA], ynB = y[mB];

    /* ---------------- layer 1: k=0..31, j and j+32 per iteration -------- */
    uint32_t hn16[64];
    {
        #pragma unroll 1
        for (int j = 0; j < 32; ++j) {
            const int j2 = j + 32;
            const ulonglong2* wi0 = (const ulonglong2*)(sW1 + j * 32);
            const ulonglong2* wg0 = (const ulonglong2*)(sW1 + (64 + j) * 32);
            const ulonglong2* wo0 = (const ulonglong2*)(sW1 + (128 + j) * 32);
            const ulonglong2* wi1 = (const ulonglong2*)(sW1 + j2 * 32);
            const ulonglong2* wg1 = (const ulonglong2*)(sW1 + (64 + j2) * 32);
            const ulonglong2* wo1 = (const ulonglong2*)(sW1 + (128 + j2) * 32);
            u64 aiA0 = pack2(fmaf(ynA, sV[j], sC[j]), 0.f);
            u64 aiB0 = pack2(fmaf(ynB, sV[j], sC[j]), 0.f);
            u64 agA0 = pack2(fmaf(ynA, sV[64 + j], sC[64 + j]), 0.f);
            u64 agB0 = pack2(fmaf(ynB, sV[64 + j], sC[64 + j]), 0.f);
            u64 aoA0 = pack2(fmaf(ynA, sV[128 + j], sC[128 + j]), 0.f);
            u64 aoB0 = pack2(fmaf(ynB, sV[128 + j], sC[128 + j]), 0.f);
            u64 aiA1 = pack2(fmaf(ynA, sV[j2], sC[j2]), 0.f);
            u64 aiB1 = pack2(fmaf(ynB, sV[j2], sC[j2]), 0.f);
            u64 agA1 = pack2(fmaf(ynA, sV[64 + j2], sC[64 + j2]), 0.f);
            u64 agB1 = pack2(fmaf(ynB, sV[64 + j2], sC[64 + j2]), 0.f);
            u64 aoA1 = pack2(fmaf(ynA, sV[128 + j2], sC[128 + j2]), 0.f);
            u64 aoB1 = pack2(fmaf(ynB, sV[128 + j2], sC[128 + j2]), 0.f);
            #pragma unroll
            for (int q = 0; q < 8; ++q) {
                ulonglong2 vi0 = wi0[q], vg0 = wg0[q], vo0 = wo0[q];
                ulonglong2 vi1 = wi1[q], vg1 = wg1[q], vo1 = wo1[q];
                u64 a0 = h2A[2 * q], a1 = h2A[2 * q + 1];
                u64 b0 = h2B[2 * q], b1 = h2B[2 * q + 1];
                aiA0 = ffma2(vi0.x, a0, aiA0); aiB0 = ffma2(vi0.x, b0, aiB0);
                agA0 = ffma2(vg0.x, a0, agA0); agB0 = ffma2(vg0.x, b0, agB0);
                aoA0 = ffma2(vo0.x, a0, aoA0); aoB0 = ffma2(vo0.x, b0, aoB0);
                aiA1 = ffma2(vi1.x, a0, aiA1); aiB1 = ffma2(vi1.x, b0, aiB1);
                agA1 = ffma2(vg1.x, a0, agA1); agB1 = ffma2(vg1.x, b0, agB1);
                aoA1 = ffma2(vo1.x, a0, aoA1); aoB1 = ffma2(vo1.x, b0, aoB1);
                aiA0 = ffma2(vi0.y, a1, aiA0); aiB0 = ffma2(vi0.y, b1, aiB0);
                agA0 = ffma2(vg0.y, a1, agA0); agB0 = ffma2(vg0.y, b1, agB0);
                aoA0 = ffma2(vo0.y, a1, aoA0); aoB0 = ffma2(vo0.y, b1, aoB0);
                aiA1 = ffma2(vi1.y, a1, aiA1); aiB1 = ffma2(vi1.y, b1, aiB1);
                agA1 = ffma2(vg1.y, a1, agA1); agB1 = ffma2(vg1.y, b1, agB1);
                aoA1 = ffma2(vo1.y, a1, aoA1); aoB1 = ffma2(vo1.y, b1, aoB1);
            }
            float hA0, hB0, hA1, hB1;
            gate_act(aiA0, agA0, aoA0, hA0);
            gate_act(aiB0, agB0, aoB0, hB0);
            gate_act(aiA1, agA1, aoA1, hA1);
            gate_act(aiB1, agB1, aoB1, hB1);
            __half2 p0 = __floats2half2_rn(hA0, hB0);
            __half2 p1 = __floats2half2_rn(hA1, hB1);
            hn16[j]  = *(uint32_t*)&p0;
            hn16[j2] = *(uint32_t*)&p1;
        }
    }

    /* unpack hn16 -> h2A/h2B (f32 k-pair packing, 64 values per item) */
    #pragma unroll
    for (int kp = 0; kp < 32; ++kp) {
        __half2 p0 = *(__half2*)&hn16[2 * kp];
        __half2 p1 = *(__half2*)&hn16[2 * kp + 1];
        float2 f0 = __half22float2(p0);
        float2 f1 = __half22float2(p1);
        h2A[kp] = pack2(f0.x, f1.x);
        h2B[kp] = pack2(f0.y, f1.y);
    }

    /* ---------------- layer 2 + fused head (paired j's) ----------------- */
    float pmA = 0.f, psA = 0.f, pmB = 0.f, psB = 0.f;
    {
        #pragma unroll 1
        for (int j = 0; j < 32; ++j) {
            const int j2 = j + 32;
            const ulonglong2* wi0 = (const ulonglong2*)(sW2 + j * 64);
            const ulonglong2* wg0 = (const ulonglong2*)(sW2 + (64 + j) * 64);
            const ulonglong2* wo0 = (const ulonglong2*)(sW2 + (128 + j) * 64);
            const ulonglong2* wi1 = (const ulonglong2*)(sW2 + j2 * 64);
            const ulonglong2* wg1 = (const ulonglong2*)(sW2 + (64 + j2) * 64);
            const ulonglong2* wo1 = (const ulonglong2*)(sW2 + (128 + j2) * 64);
            u64 aiA0 = pack2(sB2[j], 0.f),        aiB0 = aiA0;
            u64 agA0 = pack2(sB2[64 + j], 0.f),   agB0 = agA0;
            u64 aoA0 = pack2(sB2[128 + j], 0.f),  aoB0 = aoA0;
            u64 aiA1 = pack2(sB2[j2], 0.f),       aiB1 = aiA1;
            u64 agA1 = pack2(sB2[64 + j2], 0.f),  agB1 = agA1;
            u64 aoA1 = pack2(sB2[128 + j2], 0.f), aoB1 = aoA1;
            #pragma unroll
            for (int q = 0; q < 16; ++q) {
                ulonglong2 vi0 = wi0[q], vg0 = wg0[q], vo0 = wo0[q];
                ulonglong2 vi1 = wi1[q], vg1 = wg1[q], vo1 = wo1[q];
                u64 a0 = h2A[2 * q], a1 = h2A[2 * q + 1];
                u64 b0 = h2B[2 * q], b1 = h2B[2 * q + 1];
                aiA0 = ffma2(vi0.x, a0, aiA0); aiB0 = ffma2(vi0.x, b0, aiB0);
                agA0 = ffma2(vg0.x, a0, agA0); agB0 = ffma2(vg0.x, b0, agB0);
                aoA0 = ffma2(vo0.x, a0, aoA0); aoB0 = ffma2(vo0.x, b0, aoB0);
                aiA1 = ffma2(vi1.x, a0, aiA1); aiB1 = ffma2(vi1.x, b0, aiB1);
                agA1 = ffma2(vg1.x, a0, agA1); agB1 = ffma2(vg1.x, b0, agB1);
                aoA1 = ffma2(vo1.x, a0, aoA1); aoB1 = ffma2(vo1.x, b0, aoB1);
                aiA0 = ffma2(vi0.y, a1, aiA0); aiB0 = ffma2(vi0.y, b1, aiB0);
                agA0 = ffma2(vg0.y, a1, agA0); agB0 = ffma2(vg0.y, b1, agB0);
                aoA0 = ffma2(vo0.y, a1, aoA0); aoB0 = ffma2(vo0.y, b1, aoB0);
                aiA1 = ffma2(vi1.y, a1, aiA1); aiB1 = ffma2(vi1.y, b1, aiB1);
                agA1 = ffma2(vg1.y, a1, agA1); agB1 = ffma2(vg1.y, b1, agB1);
                aoA1 = ffma2(vo1.y, a1, aoA1); aoB1 = ffma2(vo1.y, b1, aoB1);
            }
            float hA0, hB0, hA1, hB1;
            gate_act(aiA0, agA0, aoA0, hA0);
            gate_act(aiB0, agB0, aoB0, hB0);
            gate_act(aiA1, agA1, aoA1, hA1);
            gate_act(aiB1, agB1, aoB1, hB1);
            float rA0 = fmaxf(hA0, 0.f), rB0 = fmaxf(hB0, 0.f);
            float rA1 = fmaxf(hA1, 0.f), rB1 = fmaxf(hB1, 0.f);
            float wm0 = sWmu[j], ws0 = sWsg[j];
            float wm1 = sWmu[j2], ws1 = sWsg[j2];
            pmA = fmaf(rA0, wm0, pmA); pmA = fmaf(rA1, wm1, pmA);
            pmB = fmaf(rB0, wm0, pmB); pmB = fmaf(rB1, wm1, pmB);
            psA = fmaf(rA0, ws0, psA); psA = fmaf(rA1, ws1, psA);
            psB = fmaf(rB0, ws0, psB); psB = fmaf(rB1, ws1, psB);
        }
    }

    const float bmu = b_mu[0], bsg = b_sigma[0];
    {
        const int n = mA / SEQ_LEN, t = mA % SEQ_LEN;
        out_mu[n * TTOT + t] = pmA + bmu;
        out_sg[n * TTOT + t] = softplus_(psA + bsg) + 1e-6f;
    }
    {
        const int n = mB / SEQ_LEN, t = mB % SEQ_LEN;
        out_mu[n * TTOT + t] = pmB + bmu;
        out_sg[n * TTOT + t] = softplus_(psB + bsg) + 1e-6f;
    }
}

extern "C" void kernel_launch(void* const* d_in, const int* in_sizes, int n_in,
                              void* d_out, int out_size)
{
    const float* X       = (const float*)d_in[0];
    const float* y       = (const float*)d_in[1];
    const float* Xf      = (const float*)d_in[2];
    const float* W_embed = (const float*)d_in[3];
    const float* b_embed = (const float*)d_in[4];
    const float* W_ih    = (const float*)d_in[5];
    const float* b_ih    = (const float*)d_in[6];
    const float* b_hh    = (const float*)d_in[7];
    const float* W_mu    = (const float*)d_in[8];
    const float* b_mu    = (const float*)d_in[9];
    const float* W_sigma = (const float*)d_in[10];
    const float* b_sigma = (const float*)d_in[11];
    float* out = (float*)d_out;

    static bool attr_done = false;
    if (!attr_done) {
        cudaFuncSetAttribute(deepar_v14,
            cudaFuncAttributeMaxDynamicSharedMemorySize, SMEM_TOTAL);
        attr_done = true;
    }

    deepar_v14<<<GRID_B + NCTA_A, BLK, SMEM_TOTAL>>>(
        X, y, Xf, W_embed, b_embed, W_ih, b_ih, b_hh,
        W_mu, b_mu, W_sigma, b_sigma, out);
}

// round 15
// speedup vs baseline: 1.7121x; 1.1140x over previous
#include <cuda_runtime.h>
#include <cuda_fp16.h>
#include <math.h>
#include <stdint.h>

#define NTS      4096
#define SEQ_LEN  168
#define HORIZON  24
#define TTOT     (SEQ_LEN + HORIZON)
#define F_IN     32
#define EMBED    32
#define HIDDEN   64
#define LAYERS   2

#define BLK      128
#define GRID_B   1024                    /* 1024 x 4 warps = 4096 series */
#define NCTA_A   (NTS * SEQ_LEN / 128)   /* 5376 CTAs x 128 items */

/* ---- smem byte offsets ----
   B-role: W1T f32[32][192] at 0 (24576), W2T f32[64][192] at 24576 (49152)
   A-role: fp16 tiles + staging (all below 66048, overlapping B regions)   */
#define OFF_W1T     0
#define OFF_W2T     24576
#define OFF_W1H     0                    /* A: fp16 [192][32] = 12288 */
#define OFF_W2H     12288                /* A: fp16 [192][64] = 24576 */
#define OFF_X16     36864                /* A: fp16 [128][32] = 8192  */
#define OFF_H16     45056                /* A: fp16 [128][64] = 16384 */
#define OFF_Y       61440                /* A: f32 [128] */
#define OFF_PM      61952                /* A: f32 [4][128] */
#define OFF_PS      64000                /* A: f32 [4][128] */
#define OFF_V       73728                /* f32[192] rank-1 y coefficient */
#define OFF_C       74496                /* f32[192] folded layer-1 bias  */
#define OFF_B2      75264                /* f32[192] layer-2 bias         */
#define OFF_SWE     76032
#define OFF_SBE     76160
#define OFF_SWMU    76288
#define OFF_SWSG    76544
#define OFF_SH      76800                /* B role: 4 warps x 64 floats   */
#define SMEM_TOTAL  77824

typedef unsigned long long u64;

__device__ __forceinline__ float ex2f(float x) {
    float r; asm("ex2.approx.f32 %0, %1;" : "=f"(r) : "f"(x)); return r;
}
__device__ __forceinline__ float rcpf(float x) {
    float r; asm("rcp.approx.f32 %0, %1;" : "=f"(r) : "f"(x)); return r;
}
__device__ __forceinline__ float sigm(float x) {
    return rcpf(1.0f + ex2f(-1.4426950408889634f * x));
}
__device__ __forceinline__ float tanh_(float x) {
    return 1.0f - 2.0f * rcpf(1.0f + ex2f(2.8853900817779268f * x));
}
__device__ __forceinline__ float softplus_(float x) {
    return (x > 20.0f) ? x : log1pf(ex2f(1.4426950408889634f * x));
}
__device__ __forceinline__ int src_row(int r) { return r + ((r >= 64) ? 64 : 0); }

__device__ __forceinline__ void mma_16816(float* d, const uint32_t* a,
                                          const uint32_t* b) {
    asm volatile(
        "mma.sync.aligned.m16n8k16.row.col.f32.f16.f16.f32 "
        "{%0,%1,%2,%3}, {%4,%5,%6,%7}, {%8,%9}, {%0,%1,%2,%3};"
        : "+f"(d[0]), "+f"(d[1]), "+f"(d[2]), "+f"(d[3])
        : "r"(a[0]), "r"(a[1]), "r"(a[2]), "r"(a[3]), "r"(b[0]), "r"(b[1]));
}

__global__ void __launch_bounds__(BLK, 2) deepar_v15(
    const float* __restrict__ X, const float* __restrict__ y,
    const float* __restrict__ Xf,
    const float* __restrict__ W_embed, const float* __restrict__ b_embed,
    const float* __restrict__ W_ih, const float* __restrict__ b_ih,
    const float* __restrict__ b_hh,
    const float* __restrict__ W_mu, const float* __restrict__ b_mu,
    const float* __restrict__ W_sigma, const float* __restrict__ b_sigma,
    float* __restrict__ out)
{
    extern __shared__ char sm[];
    float* sV   = (float*)(sm + OFF_V);
    float* sC   = (float*)(sm + OFF_C);
    float* sB2  = (float*)(sm + OFF_B2);
    float* sWe  = (float*)(sm + OFF_SWE);
    float* sBe  = (float*)(sm + OFF_SBE);
    float* sWmu = (float*)(sm + OFF_SWMU);
    float* sWsg = (float*)(sm + OFF_SWSG);

    const int tid  = threadIdx.x;
    const int lane = tid & 31;
    const int wid  = tid >> 5;
    const bool isB = (blockIdx.x < GRID_B);

    float* out_mu = out + NTS * HORIZON;
    float* out_sg = out_mu + NTS * TTOT;

    if (tid < 32) { sWe[tid] = W_embed[tid]; sBe[tid] = b_embed[tid]; }
    if (tid < 64) { sWmu[tid] = W_mu[tid]; sWsg[tid] = W_sigma[tid]; }

    /* rank-1 fold for layer 1 */
    for (int r = tid; r < 192; r += BLK) {
        int sr = src_row(r);
        const float* wy = W_ih + sr * 64 + 32;
        float v = 0.f, c = b_ih[sr] + b_hh[sr];
        #pragma unroll
        for (int e = 0; e < 32; ++e) {
            v = fmaf(wy[e], W_embed[e], v);
            c = fmaf(wy[e], b_embed[e], c);
        }
        sV[r] = v; sC[r] = c;
    }
    for (int r = tid; r < 192; r += BLK) {
        int sr = 256 + src_row(r);
        sB2[r] = b_ih[sr] + b_hh[sr];
    }

    if (isB) {
        /* ============ Phase B (unchanged from R14) ======================= */
        float* sWT1 = (float*)(sm + OFF_W1T);
        float* sWT2 = (float*)(sm + OFF_W2T);
        for (int idx = tid; idx < 32 * 192; idx += BLK) {
            int k = idx / 192, r = idx % 192;
            sWT1[idx] = W_ih[src_row(r) * 64 + k];
        }
        for (int idx = tid; idx < 64 * 192; idx += BLK) {
            int k = idx / 192, r = idx % 192;
            sWT2[idx] = W_ih[16384 + src_row(r) * 64 + k];
        }
        __syncthreads();

        const int n = blockIdx.x * 4 + wid;
        float* sh = (float*)(sm + OFF_SH) + wid * 64;
        const float bmu = b_mu[0], bsg = b_sigma[0];
        const float wmu0 = sWmu[lane], wmu1 = sWmu[32 + lane];
        const float wsg0 = sWsg[lane], wsg1 = sWsg[32 + lane];
        const float v0 = sV[lane],       v1 = sV[64 + lane],  v2 = sV[128 + lane];
        const float v3 = sV[32 + lane],  v4 = sV[96 + lane],  v5 = sV[160 + lane];
        const float c0i = sC[lane],      c1i = sC[64 + lane], c2i = sC[128 + lane];
        const float c3i = sC[32 + lane], c4i = sC[96 + lane], c5i = sC[160 + lane];

        float carry = 0.0f;
        for (int sp = 0; sp <= HORIZON; ++sp) {
            const bool seed = (sp == 0);
            const float yn = seed ? y[(size_t)n * SEQ_LEN + (SEQ_LEN - 1)] : carry;
            const float* xsrc = seed
                ? (X + ((size_t)n * SEQ_LEN + (SEQ_LEN - 1)) * F_IN)
                : (Xf + ((size_t)n * HORIZON + (sp - 1)) * F_IN);

            sh[lane] = xsrc[lane];
            __syncwarp();

            float a0 = fmaf(yn, v0, c0i), a1 = fmaf(yn, v1, c1i);
            float a2 = fmaf(yn, v2, c2i), a3 = fmaf(yn, v3, c3i);
            float a4 = fmaf(yn, v4, c4i), a5 = fmaf(yn, v5, c5i);
            #pragma unroll
            for (int k = 0; k < 32; ++k) {
                const float hk = sh[k];
                const float* row = sWT1 + k * 192;
                a0 = fmaf(row[lane],       hk, a0);
                a1 = fmaf(row[64 + lane],  hk, a1);
                a2 = fmaf(row[128 + lane], hk, a2);
                a3 = fmaf(row[32 + lane],  hk, a3);
                a4 = fmaf(row[96 + lane],  hk, a4);
                a5 = fmaf(row[160 + lane], hk, a5);
            }
            float cc0 = sigm(a0) * tanh_(a1);
            float h0  = sigm(a2) * tanh_(cc0);
            float cc1 = sigm(a3) * tanh_(a4);
            float h1  = sigm(a5) * tanh_(cc1);
            __syncwarp();
            sh[lane] = h0; sh[32 + lane] = h1;
            __syncwarp();

            a0 = sB2[lane];      a1 = sB2[64 + lane];  a2 = sB2[128 + lane];
            a3 = sB2[32 + lane]; a4 = sB2[96 + lane];  a5 = sB2[160 + lane];
            #pragma unroll
            for (int k = 0; k < 64; ++k) {
                const float hk = sh[k];
                const float* row = sWT2 + k * 192;
                a0 = fmaf(row[lane],       hk, a0);
                a1 = fmaf(row[64 + lane],  hk, a1);
                a2 = fmaf(row[128 + lane], hk, a2);
                a3 = fmaf(row[32 + lane],  hk, a3);
                a4 = fmaf(row[96 + lane],  hk, a4);
                a5 = fmaf(row[160 + lane], hk, a5);
            }
            cc0 = sigm(a0) * tanh_(a1);
            h0  = sigm(a2) * tanh_(cc0);
            cc1 = sigm(a3) * tanh_(a4);
            h1  = sigm(a5) * tanh_(cc1);

            float r0 = fmaxf(h0, 0.0f), r1 = fmaxf(h1, 0.0f);
            float pm = r0 * wmu0 + r1 * wmu1;
            float ps = r0 * wsg0 + r1 * wsg1;
            #pragma unroll
            for (int off = 16; off; off >>= 1) {
                pm += __shfl_xor_sync(0xFFFFFFFFu, pm, off);
                ps += __shfl_xor_sync(0xFFFFFFFFu, ps, off);
            }
            float mu = pm + bmu;
            float sigma = softplus_(ps + bsg) + 1e-6f;
            float s2 = sigma * sigma;
            float d = yn - mu;
            float lik = rsqrtf(2.0f * (float)M_PI * s2) *
                        ex2f(-1.4426950408889634f * (d * d) / (2.0f * s2));

            if (lane == 0) {
                if (seed) {
                    out[n * HORIZON] = lik;
                } else {
                    const int t = SEQ_LEN + sp - 1;
                    out_mu[n * TTOT + t] = mu;
                    out_sg[n * TTOT + t] = sigma;
                    if (sp <= HORIZON - 1) out[n * HORIZON + sp] = lik;
                }
            }
            carry = lik;
        }
        return;
    }

    /* ============ Phase A: HMMA (mma.sync m16n8k16 fp16) ================ */
    const int aBase = (blockIdx.x - GRID_B) * 128;

    __half* sW1h = (__half*)(sm + OFF_W1H);
    __half* sW2h = (__half*)(sm + OFF_W2H);
    float*  sY   = (float*)(sm + OFF_Y);

    for (int idx = tid; idx < 192 * 32; idx += BLK) {
        int r = idx >> 5, k = idx & 31;
        sW1h[idx] = __float2half(W_ih[src_row(r) * 64 + k]);
    }
    for (int idx = tid; idx < 192 * 64; idx += BLK) {
        int r = idx >> 6, k = idx & 63;
        sW2h[idx] = __float2half(W_ih[16384 + src_row(r) * 64 + k]);
    }
    {
        uint32_t* Xu = (uint32_t*)(sm + OFF_X16);
        const float4* xp = (const float4*)(X + (size_t)(aBase + tid) * F_IN);
        #pragma unroll
        for (int q = 0; q < 8; ++q) {
            float4 v = xp[q];
            __half2 lo = __floats2half2_rn(v.x, v.y);
            __half2 hi = __floats2half2_rn(v.z, v.w);
            Xu[tid * 16 + 2 * q]     = *(uint32_t*)&lo;
            Xu[tid * 16 + 2 * q + 1] = *(uint32_t*)&hi;
        }
        sY[tid] = y[aBase + tid];
    }
    __syncthreads();

    const uint32_t* W1u = (const uint32_t*)(sm + OFF_W1H);
    const uint32_t* W2u = (const uint32_t*)(sm + OFF_W2H);
    const uint32_t* Xu  = (const uint32_t*)(sm + OFF_X16);
    uint32_t* Hu = (uint32_t*)(sm + OFF_H16);
    float* sPM = (float*)(sm + OFF_PM);
    float* sPS = (float*)(sm + OFF_PS);

    const int jb = 16 * wid;
    const int lq = lane >> 2;   /* 0..7  : fragment row/col group */
    const int lr = lane & 3;    /* 0..3  */

    /* hoisted L1 B fragments: [gate][ntile][kc][2] */
    uint32_t B1[3][2][2][2];
    #pragma unroll
    for (int g = 0; g < 3; ++g)
        #pragma unroll
        for (int t = 0; t < 2; ++t) {
            int n = g * 64 + jb + t * 8 + lq;
            #pragma unroll
            for (int kc = 0; kc < 2; ++kc) {
                B1[g][t][kc][0] = W1u[n * 16 + kc * 8 + lr];
                B1[g][t][kc][1] = W1u[n * 16 + kc * 8 + 4 + lr];
            }
        }

    /* ---------------- layer 1 ---------------- */
    #pragma unroll 1
    for (int mc = 0; mc < 4; ++mc) {
        const int mb = mc * 32;
        float acc[3][2][2][4];
        #pragma unroll
        for (int g = 0; g < 3; ++g)
            #pragma unroll
            for (int t = 0; t < 2; ++t)
                #pragma unroll
                for (int mt = 0; mt < 2; ++mt) {
                    int r0 = mb + mt * 16 + lq;
                    int n0 = g * 64 + jb + t * 8 + lr * 2;
                    float y0 = sY[r0], y1 = sY[r0 + 8];
                    acc[g][t][mt][0] = fmaf(y0, sV[n0], sC[n0]);
                    acc[g][t][mt][1] = fmaf(y0, sV[n0 + 1], sC[n0 + 1]);
                    acc[g][t][mt][2] = fmaf(y1, sV[n0], sC[n0]);
                    acc[g][t][mt][3] = fmaf(y1, sV[n0 + 1], sC[n0 + 1]);
                }
        #pragma unroll
        for (int kc = 0; kc < 2; ++kc) {
            uint32_t A[2][4];
            #pragma unroll
            for (int mt = 0; mt < 2; ++mt) {
                int r0 = mb + mt * 16 + lq;
                A[mt][0] = Xu[r0 * 16 + kc * 8 + lr];
                A[mt][1] = Xu[(r0 + 8) * 16 + kc * 8 + lr];
                A[mt][2] = Xu[r0 * 16 + kc * 8 + 4 + lr];
                A[mt][3] = Xu[(r0 + 8) * 16 + kc * 8 + 4 + lr];
            }
            #pragma unroll
            for (int g = 0; g < 3; ++g)
                #pragma unroll
                for (int t = 0; t < 2; ++t)
                    #pragma unroll
                    for (int mt = 0; mt < 2; ++mt)
                        mma_16816(acc[g][t][mt], A[mt], B1[g][t][kc]);
        }
        /* epilogue: activations -> fp16 h */
        #pragma unroll
        for (int t = 0; t < 2; ++t)
            #pragma unroll
            for (int mt = 0; mt < 2; ++mt) {
                int r0 = mb + mt * 16 + lq;
                int cu = 8 * wid + t * 4 + lr;
                float cA = sigm(acc[0][t][mt][0]) * tanh_(acc[1][t][mt][0]);
                float h0 = sigm(acc[2][t][mt][0]) * tanh_(cA);
                float cB = sigm(acc[0][t][mt][1]) * tanh_(acc[1][t][mt][1]);
                float h1 = sigm(acc[2][t][mt][1]) * tanh_(cB);
                __half2 p0 = __floats2half2_rn(h0, h1);
                Hu[r0 * 32 + cu] = *(uint32_t*)&p0;
                float cC = sigm(acc[0][t][mt][2]) * tanh_(acc[1][t][mt][2]);
                float h2 = sigm(acc[2][t][mt][2]) * tanh_(cC);
                float cD = sigm(acc[0][t][mt][3]) * tanh_(acc[1][t][mt][3]);
                float h3 = sigm(acc[2][t][mt][3]) * tanh_(cD);
                __half2 p1 = __floats2half2_rn(h2, h3);
                Hu[(r0 + 8) * 32 + cu] = *(uint32_t*)&p1;
            }
    }
    __syncthreads();

    /* ---------------- layer 2 + head ---------------- */
    #pragma unroll 1
    for (int mc = 0; mc < 4; ++mc) {
        const int mb = mc * 32;
        float acc[3][2][2][4];
        #pragma unroll
        for (int g = 0; g < 3; ++g)
            #pragma unroll
            for (int t = 0; t < 2; ++t) {
                int n0 = g * 64 + jb + t * 8 + lr * 2;
                float b0 = sB2[n0], b1 = sB2[n0 + 1];
                #pragma unroll
                for (int mt = 0; mt < 2; ++mt) {
                    acc[g][t][mt][0] = b0; acc[g][t][mt][1] = b1;
                    acc[g][t][mt][2] = b0; acc[g][t][mt][3] = b1;
                }
            }
        #pragma unroll
        for (int kc = 0; kc < 4; ++kc) {
            uint32_t A[2][4];
            #pragma unroll
            for (int mt = 0; mt < 2; ++mt) {
                int r0 = mb + mt * 16 + lq;
                A[mt][0] = Hu[r0 * 32 + kc * 8 + lr];
                A[mt][1] = Hu[(r0 + 8) * 32 + kc * 8 + lr];
                A[mt][2] = Hu[r0 * 32 + kc * 8 + 4 + lr];
                A[mt][3] = Hu[(r0 + 8) * 32 + kc * 8 + 4 + lr];
            }
            #pragma unroll
            for (int g = 0; g < 3; ++g)
                #pragma unroll
                for (int t = 0; t < 2; ++t) {
                    int n = g * 64 + jb + t * 8 + lq;
                    uint32_t Bv[2];
                    Bv[0] = W2u[n * 32 + kc * 8 + lr];
                    Bv[1] = W2u[n * 32 + kc * 8 + 4 + lr];
                    #pragma unroll
                    for (int mt = 0; mt < 2; ++mt)
                        mma_16816(acc[g][t][mt], A[mt], Bv);
                }
        }
        /* epilogue: activations + relu + head partials */
        #pragma unroll
        for (int mt = 0; mt < 2; ++mt) {
            int r0 = mb + mt * 16 + lq;
            float pm0 = 0.f, ps0 = 0.f, pm1 = 0.f, ps1 = 0.f;
            #pragma unroll
            for (int t = 0; t < 2; ++t) {
                int j0 = jb + t * 8 + lr * 2, j1 = j0 + 1;
                float wm0 = sWmu[j0], wm1 = sWmu[j1];
                float ws0 = sWsg[j0], ws1 = sWsg[j1];
                float cA = sigm(acc[0][t][mt][0]) * tanh_(acc[1][t][mt][0]);
                float h0 = fmaxf(sigm(acc[2][t][mt][0]) * tanh_(cA), 0.f);
                float cB = sigm(acc[0][t][mt][1]) * tanh_(acc[1][t][mt][1]);
                float h1 = fmaxf(sigm(acc[2][t][mt][1]) * tanh_(cB), 0.f);
                float cC = sigm(acc[0][t][mt][2]) * tanh_(acc[1][t][mt][2]);
                float h2 = fmaxf(sigm(acc[2][t][mt][2]) * tanh_(cC), 0.f);
                float cD = sigm(acc[0][t][mt][3]) * tanh_(acc[1][t][mt][3]);
                float h3 = fmaxf(sigm(acc[2][t][mt][3]) * tanh_(cD), 0.f);
                pm0 = fmaf(h0, wm0, pm0); pm0 = fmaf(h1, wm1, pm0);
                ps0 = fmaf(h0, ws0, ps0); ps0 = fmaf(h1, ws1, ps0);
                pm1 = fmaf(h2, wm0, pm1); pm1 = fmaf(h3, wm1, pm1);
                ps1 = fmaf(h2, ws0, ps1); ps1 = fmaf(h3, ws1, ps1);
            }
            pm0 += __shfl_xor_sync(0xFFFFFFFFu, pm0, 1);
            pm0 += __shfl_xor_sync(0xFFFFFFFFu, pm0, 2);
            ps0 += __shfl_xor_sync(0xFFFFFFFFu, ps0, 1);
            ps0 += __shfl_xor_sync(0xFFFFFFFFu, ps0, 2);
            pm1 += __shfl_xor_sync(0xFFFFFFFFu, pm1, 1);
            pm1 += __shfl_xor_sync(0xFFFFFFFFu, pm1, 2);
            ps1 += __shfl_xor_sync(0xFFFFFFFFu, ps1, 1);
            ps1 += __shfl_xor_sync(0xFFFFFFFFu, ps1, 2);
            if (lr == 0) {
                sPM[wid * 128 + r0] = pm0;     sPS[wid * 128 + r0] = ps0;
                sPM[wid * 128 + r0 + 8] = pm1; sPS[wid * 128 + r0 + 8] = ps1;
            }
        }
    }
    __syncthreads();

    {
        float pm = sPM[tid] + sPM[128 + tid] + sPM[256 + tid] + sPM[384 + tid];
        float ps = sPS[tid] + sPS[128 + tid] + sPS[256 + tid] + sPS[384 + tid];
        const int item = aBase + tid;
        const int n = item / SEQ_LEN, t = item % SEQ_LEN;
        out_mu[n * TTOT + t] = pm + b_mu[0];
        out_sg[n * TTOT + t] = softplus_(ps + b_sigma[0]) + 1e-6f;
    }
}

extern "C" void kernel_launch(void* const* d_in, const int* in_sizes, int n_in,
                              void* d_out, int out_size)
{
    const float* X       = (const float*)d_in[0];
    const float* y       = (const float*)d_in[1];
    const float* Xf      = (const float*)d_in[2];
    const float* W_embed = (const float*)d_in[3];
    const float* b_embed = (const float*)d_in[4];
    const float* W_ih    = (const float*)d_in[5];
    const float* b_ih    = (const float*)d_in[6];
    const float* b_hh    = (const float*)d_in[7];
    const float* W_mu    = (const float*)d_in[8];
    const float* b_mu    = (const float*)d_in[9];
    const float* W_sigma = (const float*)d_in[10];
    const float* b_sigma = (const float*)d_in[11];
    float* out = (float*)d_out;

    static bool attr_done = false;
    if (!attr_done) {
        cudaFuncSetAttribute(deepar_v15,
            cudaFuncAttributeMaxDynamicSharedMemorySize, SMEM_TOTAL);
        attr_done = true;
    }

    deepar_v15<<<GRID_B + NCTA_A, BLK, SMEM_TOTAL>>>(
        X, y, Xf, W_embed, b_embed, W_ih, b_ih, b_hh,
        W_mu, b_mu, W_sigma, b_sigma, out);
}